// round 13
// baseline (speedup 1.0000x reference)
#include <cuda_runtime.h>
#include <cuda_fp16.h>
#include <math_constants.h>
#include <cstdint>

#define H 128
#define TILE_M 32
#define NPAD 1048576
#define SEG_CAP 65536

#define RST32 528                        // fp32 stage row stride bytes (132 floats)
#define RSTB  272                        // fp16 B row stride bytes (136 elems)
#define A32_BUF 16896                    // 32 x 528

// smem layout (bytes), per CTA (x3 CTAs/SM)
#define OFF_B     0                      // 128 x 272 = 34816
#define OFF_A32   34816                  // 2 bufs x 16896 = 33792
#define OFF_SGATE 68608                  // 4 x 32 floats = 512
#define OFF_SB1   69120                  // 512
#define OFF_SW2   69632                  // 512
#define SMEM_TOTAL 70144

__device__ float d_gate[NPAD];
__device__ int   d_seg_start[SEG_CAP];
__device__ int   d_seg_end[SEG_CAP];
__device__ __half d_W1h[H * H];

// ---------------------------------------------------------------------------
__device__ __forceinline__ uint32_t smem_u32(const void* p) {
    uint32_t a;
    asm("{ .reg .u64 t; cvta.to.shared.u64 t, %1; cvt.u32.u64 %0, t; }"
        : "=r"(a) : "l"(p));
    return a;
}
__device__ __forceinline__ void ldsm_x4_t(uint32_t* r, uint32_t addr) {
    asm volatile("ldmatrix.sync.aligned.m8n8.x4.trans.shared.b16 {%0,%1,%2,%3}, [%4];"
                 : "=r"(r[0]), "=r"(r[1]), "=r"(r[2]), "=r"(r[3]) : "r"(addr));
}
__device__ __forceinline__ void mma16816h(float* d, const uint32_t* a,
                                          const uint32_t* b) {
    asm volatile(
        "mma.sync.aligned.m16n8k16.row.col.f32.f16.f16.f32 "
        "{%0,%1,%2,%3}, {%4,%5,%6,%7}, {%8,%9}, {%0,%1,%2,%3};"
        : "+f"(d[0]), "+f"(d[1]), "+f"(d[2]), "+f"(d[3])
        : "r"(a[0]), "r"(a[1]), "r"(a[2]), "r"(a[3]), "r"(b[0]), "r"(b[1]));
}
__device__ __forceinline__ void cp_async16(uint32_t dst, const void* src, int sz) {
    asm volatile("cp.async.cg.shared.global [%0], [%1], 16, %2;"
                 :: "r"(dst), "l"(src), "r"(sz) : "memory");
}
#define CP_COMMIT() asm volatile("cp.async.commit_group;" ::: "memory")
#define CP_WAIT0()  asm volatile("cp.async.wait_group 0;" ::: "memory")
#define CP_WAIT1()  asm volatile("cp.async.wait_group 1;" ::: "memory")

__device__ __forceinline__ float2 lds_f2(uint32_t addr) {
    float2 v;
    asm volatile("ld.shared.v2.f32 {%0,%1}, [%2];"
                 : "=f"(v.x), "=f"(v.y) : "r"(addr));
    return v;
}
__device__ __forceinline__ uint32_t pack_h2(float2 v) {
    __half2 h = __floats2half2_rn(v.x, v.y);
    return *(uint32_t*)&h;
}

// ---------------------------------------------------------------------------
// Segment bounds
// ---------------------------------------------------------------------------
__global__ void init_bounds_kernel(int B) {
    int b = blockIdx.x * blockDim.x + threadIdx.x;
    if (b < B) { d_seg_start[b] = -1; d_seg_end[b] = -1; }
}
__global__ void bounds_kernel(const int* __restrict__ bi, int N) {
    int n = blockIdx.x * blockDim.x + threadIdx.x;
    if (n >= N) return;
    int b = bi[n];
    if (n == 0 || bi[n - 1] != b) d_seg_start[b] = n;
    if (n == N - 1 || bi[n + 1] != b) d_seg_end[b] = n + 1;
}

// ---------------------------------------------------------------------------
// W1 -> fp16 (runs once)
// ---------------------------------------------------------------------------
__global__ void prep_w1_kernel(const float* __restrict__ W1) {
    int idx = blockIdx.x * blockDim.x + threadIdx.x;
    if (idx >= H * H) return;
    d_W1h[idx] = __float2half_rn(W1[idx]);
}

__device__ __forceinline__ void issue_cp(const float* __restrict__ x, uint32_t sb,
                                         long t, int buf, int N, int tid) {
    long m0 = t * TILE_M;
    uint32_t dst0 = sb + OFF_A32 + buf * A32_BUF;
#pragma unroll
    for (int c = 0; c < 4; c++) {
        int chunk = c * 256 + tid;           // 1024 chunks of 16B
        int row = chunk >> 5, col16 = chunk & 31;
        long gm = m0 + row;
        const float* src = x + (size_t)(gm < N ? gm : 0) * H + col16 * 4;
        cp_async16(dst0 + row * RST32 + col16 * 16, src, gm < N ? 16 : 0);
    }
    CP_COMMIT();
}

// ---------------------------------------------------------------------------
// Gate kernel: persistent, 3 CTAs/SM. CTA = 32x128 tile, single fp16 product.
// 256 thr = 8 warps (2M x 4N), warp tile 16x32 (acc 16 regs). A floats + B
// fragments prefetched one k ahead; cp.async double-buffered fp32 stage.
// ---------------------------------------------------------------------------
__global__ __launch_bounds__(256, 3) void gate_mma_kernel(
    const float* __restrict__ x, const float* __restrict__ b1,
    const float* __restrict__ W2, int N)
{
    extern __shared__ char smem[];
    const uint32_t sb = smem_u32(smem);
    const int tid = threadIdx.x;
    const int wid = tid >> 5, lane = tid & 31;
    const int warp_m = wid & 1;          // rows warp_m*16
    const int warp_n = wid >> 1;         // cols warp_n*32
    const long tile0 = blockIdx.x;
    const long tstride = gridDim.x;

    float* sgate = (float*)(smem + OFF_SGATE);
    float* sb1   = (float*)(smem + OFF_SB1);
    float* sw2   = (float*)(smem + OFF_SW2);
    if (tid < H) { sb1[tid] = b1[tid]; sw2[tid] = W2[tid]; }

    const int numTiles = (N + TILE_M - 1) / TILE_M;

    if (tile0 < numTiles) issue_cp(x, sb, tile0, 0, N, tid);

    // B (W1 fp16) -> smem once: 2048 uint4
#pragma unroll
    for (int c = 0; c < 8; c++) {
        int idx = c * 256 + tid;
        int k = idx >> 4, n8 = (idx & 15) << 3;
        uint32_t off = (uint32_t)k * RSTB + (uint32_t)n8 * 2;
        *(uint4*)(smem + OFF_B + off) = *(const uint4*)(d_W1h + k * H + n8);
    }

    if (tile0 + tstride < numTiles) issue_cp(x, sb, tile0 + tstride, 1, N, tid);

    // per-lane addresses
    const int fr = lane >> 2;            // 0..7
    const int fc = (lane & 3) * 2;       // 0,2,4,6
    const uint32_t a_base = sb + OFF_A32
                          + (uint32_t)(warp_m * 16 + fr) * RST32 + (uint32_t)fc * 4;
    const uint32_t b_base = sb + OFF_B + (uint32_t)(lane & 15) * RSTB
                          + (uint32_t)(warp_n * 32 + (lane >> 4) * 8) * 2;

    int buf = 0;
    for (long t = tile0; t < numTiles; t += tstride, buf ^= 1) {
        const bool hn  = (t + tstride)     < numTiles;
        const bool hnn = (t + 2 * tstride) < numTiles;

        if (hn) { CP_WAIT1(); } else { CP_WAIT0(); }
        __syncthreads();                 // A32[buf] visible; sgate free

        float acc[4][4];
#pragma unroll
        for (int ni = 0; ni < 4; ni++)
#pragma unroll
            for (int r = 0; r < 4; r++) acc[ni][r] = 0.f;

        const uint32_t aK = a_base + (uint32_t)buf * A32_BUF;

        // k=0 A floats + B fragments
        float2 f0 = lds_f2(aK);
        float2 f1 = lds_f2(aK + 8 * RST32);
        float2 f2 = lds_f2(aK + 32);
        float2 f3 = lds_f2(aK + 8 * RST32 + 32);
        uint32_t bfr[2][2][4];           // [pingpong][nb][frag]
#pragma unroll
        for (int nb = 0; nb < 2; nb++)
            ldsm_x4_t(bfr[0][nb], b_base + nb * 32);

#pragma unroll
        for (int k = 0; k < 8; k++) {
            const int cur = k & 1, nxt = cur ^ 1;
            uint32_t ah[4];
            ah[0] = pack_h2(f0);
            ah[1] = pack_h2(f1);
            ah[2] = pack_h2(f2);
            ah[3] = pack_h2(f3);

            if (k < 7) {
                const uint32_t an = aK + (uint32_t)(k + 1) * 64;
                f0 = lds_f2(an);
                f1 = lds_f2(an + 8 * RST32);
                f2 = lds_f2(an + 32);
                f3 = lds_f2(an + 8 * RST32 + 32);
                const uint32_t bn = b_base + (uint32_t)(k + 1) * 16 * RSTB;
#pragma unroll
                for (int nb = 0; nb < 2; nb++)
                    ldsm_x4_t(bfr[nxt][nb], bn + nb * 32);
            }

            // 4 HMMA, each accumulator written once per k-step
#pragma unroll
            for (int nb = 0; nb < 2; nb++) {
                mma16816h(acc[nb * 2],     ah, &bfr[cur][nb][0]);
                mma16816h(acc[nb * 2 + 1], ah, &bfr[cur][nb][2]);
            }
        }

        // ---- epilogue: silu + dot(W2), warp row-reduce ----
        float part[2] = {0.f, 0.f};
#pragma unroll
        for (int ni = 0; ni < 4; ni++)
#pragma unroll
            for (int r = 0; r < 4; r++) {
                int col = warp_n * 32 + ni * 8 + (lane & 3) * 2 + (r & 1);
                float vv = acc[ni][r] + sb1[col];
                float sl = vv / (1.f + __expf(-vv));
                part[r >> 1] = fmaf(sl, sw2[col], part[r >> 1]);
            }
#pragma unroll
        for (int hh = 0; hh < 2; hh++) {
            float p = part[hh];
            p += __shfl_xor_sync(0xFFFFFFFF, p, 1);
            p += __shfl_xor_sync(0xFFFFFFFF, p, 2);
            part[hh] = p;
        }
        if ((lane & 3) == 0) {
#pragma unroll
            for (int hh = 0; hh < 2; hh++) {
                int row = warp_m * 16 + hh * 8 + (lane >> 2);
                sgate[warp_n * 32 + row] = part[hh];
            }
        }
        __syncthreads();                 // A32[buf] reads done; sgate complete

        if (hnn) issue_cp(x, sb, t + 2 * tstride, buf, N, tid);

        if (tid < TILE_M) {
            long gm = t * TILE_M + tid;
            if (gm < N)
                d_gate[gm] = sgate[tid] + sgate[32 + tid]
                           + sgate[64 + tid] + sgate[96 + tid];
        }
    }
}

// ---------------------------------------------------------------------------
// Reduce kernel: per-segment mean/max/attention (b2 cancels in softmax)
// ---------------------------------------------------------------------------
__global__ __launch_bounds__(128) void reduce_kernel(
    const float* __restrict__ x, float* __restrict__ out)
{
    int b = blockIdx.x;
    int j = threadIdx.x;
    int s = d_seg_start[b];
    int e = (s < 0) ? 0 : d_seg_end[b];
    if (s < 0) s = 0;

    float sum = 0.f, mx = -CUDART_INF_F;
    float m0 = -CUDART_INF_F, dn0 = 0.f, ac0 = 0.f;
    float m1 = -CUDART_INF_F, dn1 = 0.f, ac1 = 0.f;

    int n = s;
    for (; n + 2 <= e; n += 2) {
        float xv0 = __ldg(x + (size_t)n * H + j);
        float g0  = d_gate[n];
        float xv1 = __ldg(x + (size_t)(n + 1) * H + j);
        float g1  = d_gate[n + 1];
        sum += xv0 + xv1;
        mx = fmaxf(mx, fmaxf(xv0, xv1));
        if (g0 > m0) { float sc = __expf(m0 - g0); dn0 *= sc; ac0 *= sc; m0 = g0; }
        float e0 = __expf(g0 - m0); dn0 += e0; ac0 = fmaf(e0, xv0, ac0);
        if (g1 > m1) { float sc = __expf(m1 - g1); dn1 *= sc; ac1 *= sc; m1 = g1; }
        float e1 = __expf(g1 - m1); dn1 += e1; ac1 = fmaf(e1, xv1, ac1);
    }
    if (n < e) {
        float xv = __ldg(x + (size_t)n * H + j);
        float g  = d_gate[n];
        sum += xv; mx = fmaxf(mx, xv);
        if (g > m0) { float sc = __expf(m0 - g); dn0 *= sc; ac0 *= sc; m0 = g; }
        float ev = __expf(g - m0); dn0 += ev; ac0 = fmaf(ev, xv, ac0);
    }

    int cnt = e - s;
    float denom = 0.f, acc = 0.f;
    if (cnt > 0) {
        float M  = fmaxf(m0, m1);
        float s0 = (m0 > -CUDART_INF_F) ? __expf(m0 - M) : 0.f;
        float s1 = (m1 > -CUDART_INF_F) ? __expf(m1 - M) : 0.f;
        denom = dn0 * s0 + dn1 * s1;
        acc   = ac0 * s0 + ac1 * s1;
    }
    float* o = out + (size_t)b * (3 * H);
    o[j]         = sum / fmaxf((float)cnt, 1.f);
    o[H + j]     = mx;
    o[2 * H + j] = (cnt > 0) ? (acc / denom) : 0.f;
}

// ---------------------------------------------------------------------------
extern "C" void kernel_launch(void* const* d_in, const int* in_sizes, int n_in,
                              void* d_out, int out_size) {
    const float* x  = (const float*)d_in[0];
    const float* W1 = (const float*)d_in[1];
    const float* b1 = (const float*)d_in[2];
    const float* W2 = (const float*)d_in[3];
    const int*   bi = (const int*)d_in[5];

    const int N = in_sizes[5];
    const int B = out_size / (3 * H);
    float* out = (float*)d_out;

    static int inited = 0;
    static int sms = 148;
    if (!inited) {
        cudaFuncSetAttribute(gate_mma_kernel,
                             cudaFuncAttributeMaxDynamicSharedMemorySize, SMEM_TOTAL);
        int dev = 0;
        cudaGetDevice(&dev);
        cudaDeviceGetAttribute(&sms, cudaDevAttrMultiProcessorCount, dev);
        inited = 1;
    }

    const int numTiles = (N + TILE_M - 1) / TILE_M;
    const int gateGrid = (3 * sms < numTiles) ? 3 * sms : numTiles;

    init_bounds_kernel<<<(B + 255) / 256, 256>>>(B);
    bounds_kernel<<<(N + 255) / 256, 256>>>(bi, N);
    prep_w1_kernel<<<(H * H + 255) / 256, 256>>>(W1);
    gate_mma_kernel<<<gateGrid, 256, SMEM_TOTAL>>>(x, b1, W2, N);
    reduce_kernel<<<B, H>>>(x, out);
}

// round 15
// speedup vs baseline: 1.0209x; 1.0209x over previous
#include <cuda_runtime.h>
#include <cuda_fp16.h>
#include <math_constants.h>
#include <cstdint>

#define H 128
#define TILE_M 64
#define NPAD 1048576
#define SEG_CAP 65536

#define RST32 528                        // fp32 stage row stride bytes (132 floats)
#define RSTH  272                        // fp16 row stride bytes (136 elems)
#define A32_BUF 33792                    // 64 x 528

// smem layout (bytes), per CTA (x2 CTAs/SM)
// W (fp16 [k][n], 128x272=34816) is used only in the prologue to fill A regs;
// the same region is then reused as the fp16 x tile (64x272=17408).
#define OFF_W     0
#define OFF_XH    0
#define OFF_A32   34816                  // 2 bufs x 33792 = 67584
#define OFF_SGATE 102400                 // 8 x 64 floats = 2048
#define SMEM_TOTAL 104448

__device__ float d_gate[NPAD];
__device__ int   d_seg_start[SEG_CAP];
__device__ int   d_seg_end[SEG_CAP];
__device__ __half d_W1h[H * H];

// ---------------------------------------------------------------------------
__device__ __forceinline__ uint32_t smem_u32(const void* p) {
    uint32_t a;
    asm("{ .reg .u64 t; cvta.to.shared.u64 t, %1; cvt.u32.u64 %0, t; }"
        : "=r"(a) : "l"(p));
    return a;
}
__device__ __forceinline__ void ldsm_x4(uint32_t* r, uint32_t addr) {
    asm volatile("ldmatrix.sync.aligned.m8n8.x4.shared.b16 {%0,%1,%2,%3}, [%4];"
                 : "=r"(r[0]), "=r"(r[1]), "=r"(r[2]), "=r"(r[3]) : "r"(addr));
}
__device__ __forceinline__ void ldsm_x4_t(uint32_t* r, uint32_t addr) {
    asm volatile("ldmatrix.sync.aligned.m8n8.x4.trans.shared.b16 {%0,%1,%2,%3}, [%4];"
                 : "=r"(r[0]), "=r"(r[1]), "=r"(r[2]), "=r"(r[3]) : "r"(addr));
}
__device__ __forceinline__ void mma16816h(float* d, const uint32_t* a,
                                          uint32_t b0, uint32_t b1) {
    asm volatile(
        "mma.sync.aligned.m16n8k16.row.col.f32.f16.f16.f32 "
        "{%0,%1,%2,%3}, {%4,%5,%6,%7}, {%8,%9}, {%0,%1,%2,%3};"
        : "+f"(d[0]), "+f"(d[1]), "+f"(d[2]), "+f"(d[3])
        : "r"(a[0]), "r"(a[1]), "r"(a[2]), "r"(a[3]), "r"(b0), "r"(b1));
}
__device__ __forceinline__ void cp_async16(uint32_t dst, const void* src, int sz) {
    asm volatile("cp.async.cg.shared.global [%0], [%1], 16, %2;"
                 :: "r"(dst), "l"(src), "r"(sz) : "memory");
}
#define CP_COMMIT() asm volatile("cp.async.commit_group;" ::: "memory")
#define CP_WAIT0()  asm volatile("cp.async.wait_group 0;" ::: "memory")
#define CP_WAIT1()  asm volatile("cp.async.wait_group 1;" ::: "memory")

__device__ __forceinline__ uint32_t pack_h2(float a, float b) {
    __half2 h = __floats2half2_rn(a, b);
    return *(uint32_t*)&h;
}

// ---------------------------------------------------------------------------
// Segment bounds
// ---------------------------------------------------------------------------
__global__ void init_bounds_kernel(int B) {
    int b = blockIdx.x * blockDim.x + threadIdx.x;
    if (b < B) { d_seg_start[b] = -1; d_seg_end[b] = -1; }
}
__global__ void bounds_kernel(const int* __restrict__ bi, int N) {
    int n = blockIdx.x * blockDim.x + threadIdx.x;
    if (n >= N) return;
    int b = bi[n];
    if (n == 0 || bi[n - 1] != b) d_seg_start[b] = n;
    if (n == N - 1 || bi[n + 1] != b) d_seg_end[b] = n + 1;
}

// ---------------------------------------------------------------------------
// W1 -> fp16 (runs once)
// ---------------------------------------------------------------------------
__global__ void prep_w1_kernel(const float* __restrict__ W1) {
    int idx = blockIdx.x * blockDim.x + threadIdx.x;
    if (idx >= H * H) return;
    d_W1h[idx] = __float2half_rn(W1[idx]);
}

__device__ __forceinline__ void issue_cp(const float* __restrict__ x, uint32_t sb,
                                         long t, int buf, int N, int tid) {
    long m0 = t * TILE_M;
    uint32_t dst0 = sb + OFF_A32 + buf * A32_BUF;
#pragma unroll
    for (int c = 0; c < 8; c++) {
        int chunk = c * 256 + tid;           // 2048 chunks of 16B
        int row = chunk >> 5, col16 = chunk & 31;
        long gm = m0 + row;
        const float* src = x + (size_t)(gm < N ? gm : 0) * H + col16 * 4;
        cp_async16(dst0 + row * RST32 + col16 * 16, src, gm < N ? 16 : 0);
    }
    CP_COMMIT();
}

// ---------------------------------------------------------------------------
// Gate kernel (operand-swapped): persistent, 2 CTAs/SM, tile 64 nodes x 128.
// 256 thr = 8 warps; warp w owns hidden cols [w*16, w*16+16) as the MMA "M"
// dim with A = W1^T fragments held in registers for the whole kernel.
// B = x tile (fp16, converted once per tile into smem; NON-trans ldmatrix
// since [node][k] storage already matches the B-fragment distribution).
// k-loop is 4 ldsm + 8 HMMA per k-step. Epilogue reduces over cols.
// ---------------------------------------------------------------------------
__global__ __launch_bounds__(256, 2) void gate_mma_kernel(
    const float* __restrict__ x, const float* __restrict__ b1,
    const float* __restrict__ W2, int N)
{
    extern __shared__ char smem[];
    const uint32_t sb = smem_u32(smem);
    const int tid = threadIdx.x;
    const int cg = tid >> 5;             // warp id = hidden-col group (0..7)
    const int lane = tid & 31;
    const long tile0 = blockIdx.x;
    const long tstride = gridDim.x;

    float* sgate = (float*)(smem + OFF_SGATE);
    const int numTiles = (N + TILE_M - 1) / TILE_M;

    if (tile0 < numTiles) issue_cp(x, sb, tile0, 0, N, tid);

    // W1 fp16 -> smem (native [k][n] layout, stride RSTH) for A-reg init
#pragma unroll
    for (int c = 0; c < 8; c++) {
        int idx = c * 256 + tid;             // 2048 uint4
        int k = idx >> 4, n8 = (idx & 15) << 3;
        *(uint4*)(smem + OFF_W + (uint32_t)k * RSTH + (uint32_t)n8 * 2) =
            *(const uint4*)(d_W1h + k * H + n8);
    }

    if (tile0 + tstride < numTiles) issue_cp(x, sb, tile0 + tstride, 1, N, tid);
    __syncthreads();                         // W visible

    // A registers: W1^T fragments for this warp's 16 cols, all 8 k-steps.
    // ldsm.trans from [k][n] storage: tile0=(n0-7,k0-7)->a0, tile1=(n0-7,
    // k8-15)->a2, tile2=(n8-15,k0-7)->a1, tile3->a3 => permute {r0,r2,r1,r3}.
    uint32_t aw[8][4];
    {
        const uint32_t wbase = sb + OFF_W + (uint32_t)(lane & 15) * RSTH
                             + (uint32_t)(cg * 16 + (lane >> 4) * 8) * 2;
#pragma unroll
        for (int k = 0; k < 8; k++) {
            uint32_t r[4];
            ldsm_x4_t(r, wbase + (uint32_t)k * 16 * RSTH);
            aw[k][0] = r[0]; aw[k][1] = r[2]; aw[k][2] = r[1]; aw[k][3] = r[3];
        }
    }

    // per-lane fixed cols for epilogue
    const int col0 = cg * 16 + (lane >> 2);
    const float b1a = __ldg(b1 + col0),     b1b = __ldg(b1 + col0 + 8);
    const float w2a = __ldg(W2 + col0),     w2b = __ldg(W2 + col0 + 8);

    // convert-pass mapping: thread handles row tid>>2, 32 cols
    const int cvr = tid >> 2;
    const int cvc = (tid & 3) * 32;
    // ldsm (non-trans) source base in xh: lanes 0-15 -> node rows 0-15 (k blk
    // 0), lanes 16-31 -> same nodes at k+8 => tiles {n-lo k-lo, n-hi k-lo,
    // n-lo k-hi, n-hi k-hi} = {r0, r1, r2, r3}
    const uint32_t xbase = sb + OFF_XH + (uint32_t)(lane & 15) * RSTH
                         + (uint32_t)((lane >> 4) * 8) * 2;

    int buf = 0;
    for (long t = tile0; t < numTiles; t += tstride, buf ^= 1) {
        const bool hn  = (t + tstride)     < numTiles;
        const bool hnn = (t + 2 * tstride) < numTiles;

        if (hn) { CP_WAIT1(); } else { CP_WAIT0(); }
        __syncthreads();                 // A32[buf] ready; xh free

        // ---- convert A32[buf] fp32 -> xh fp16 ([node][k], stride RSTH) ----
        {
            const char* a32 = smem + OFF_A32 + buf * A32_BUF
                            + (uint32_t)cvr * RST32 + (uint32_t)cvc * 4;
            char* dst = smem + OFF_XH + (uint32_t)cvr * RSTH + (uint32_t)cvc * 2;
#pragma unroll
            for (int j = 0; j < 4; j++) {
                float4 va = *(const float4*)(a32 + j * 32);
                float4 vb = *(const float4*)(a32 + j * 32 + 16);
                uint4 o;
                o.x = pack_h2(va.x, va.y); o.y = pack_h2(va.z, va.w);
                o.z = pack_h2(vb.x, vb.y); o.w = pack_h2(vb.z, vb.w);
                *(uint4*)(dst + j * 16) = o;
            }
        }
        __syncthreads();                 // xh ready

        if (hnn) issue_cp(x, sb, t + 2 * tstride, buf, N, tid);  // A32[buf] free

        // ---- MMA: per k-step 4 ldsm (64 nodes) + 8 HMMA ----
        float acc[8][4];
#pragma unroll
        for (int nt = 0; nt < 8; nt++)
#pragma unroll
            for (int r = 0; r < 4; r++) acc[nt][r] = 0.f;

#pragma unroll
        for (int k = 0; k < 8; k++) {
#pragma unroll
            for (int ng = 0; ng < 4; ng++) {
                uint32_t r[4];
                ldsm_x4(r, xbase + (uint32_t)ng * 16 * RSTH + (uint32_t)k * 32);
                // n-lo tile: b={r0, r2}; n-hi tile: b={r1, r3}
                mma16816h(acc[ng * 2],     aw[k], r[0], r[2]);
                mma16816h(acc[ng * 2 + 1], aw[k], r[1], r[3]);
            }
        }

        // ---- epilogue: silu + W2 dot (reduce over cols) ----
        // D layout: row(=hidden col) = cg*16 + (lane>>2) + (r>=2)*8,
        //           col(=node) = nt*8 + (lane&3)*2 + (r&1)
        float part[8][2];
#pragma unroll
        for (int nt = 0; nt < 8; nt++) { part[nt][0] = 0.f; part[nt][1] = 0.f; }
#pragma unroll
        for (int nt = 0; nt < 8; nt++)
#pragma unroll
            for (int r = 0; r < 4; r++) {
                float vv = acc[nt][r] + ((r & 2) ? b1b : b1a);
                float sl = vv / (1.f + __expf(-vv));
                part[nt][r & 1] = fmaf(sl, (r & 2) ? w2b : w2a, part[nt][r & 1]);
            }
        // reduce across the 8 lanes sharing (lane&3)
#pragma unroll
        for (int nt = 0; nt < 8; nt++)
#pragma unroll
            for (int bb = 0; bb < 2; bb++) {
                float p = part[nt][bb];
                p += __shfl_xor_sync(0xFFFFFFFF, p, 4);
                p += __shfl_xor_sync(0xFFFFFFFF, p, 8);
                p += __shfl_xor_sync(0xFFFFFFFF, p, 16);
                part[nt][bb] = p;
            }
        if (lane < 4) {
#pragma unroll
            for (int nt = 0; nt < 8; nt++)
#pragma unroll
                for (int bb = 0; bb < 2; bb++)
                    sgate[cg * 64 + nt * 8 + lane * 2 + bb] = part[nt][bb];
        }
        __syncthreads();                 // sgate complete; xh reads done

        if (tid < TILE_M) {
            long gm = t * TILE_M + tid;
            if (gm < N) {
                float g = 0.f;
#pragma unroll
                for (int c = 0; c < 8; c++) g += sgate[c * 64 + tid];
                d_gate[gm] = g;
            }
        }
    }
}

// ---------------------------------------------------------------------------
// Reduce kernel: per-segment mean/max/attention (b2 cancels in softmax)
// ---------------------------------------------------------------------------
__global__ __launch_bounds__(128) void reduce_kernel(
    const float* __restrict__ x, float* __restrict__ out)
{
    int b = blockIdx.x;
    int j = threadIdx.x;
    int s = d_seg_start[b];
    int e = (s < 0) ? 0 : d_seg_end[b];
    if (s < 0) s = 0;

    float sum = 0.f, mx = -CUDART_INF_F;
    float m0 = -CUDART_INF_F, dn0 = 0.f, ac0 = 0.f;
    float m1 = -CUDART_INF_F, dn1 = 0.f, ac1 = 0.f;

    int n = s;
    for (; n + 2 <= e; n += 2) {
        float xv0 = __ldg(x + (size_t)n * H + j);
        float g0  = d_gate[n];
        float xv1 = __ldg(x + (size_t)(n + 1) * H + j);
        float g1  = d_gate[n + 1];
        sum += xv0 + xv1;
        mx = fmaxf(mx, fmaxf(xv0, xv1));
        if (g0 > m0) { float sc = __expf(m0 - g0); dn0 *= sc; ac0 *= sc; m0 = g0; }
        float e0 = __expf(g0 - m0); dn0 += e0; ac0 = fmaf(e0, xv0, ac0);
        if (g1 > m1) { float sc = __expf(m1 - g1); dn1 *= sc; ac1 *= sc; m1 = g1; }
        float e1 = __expf(g1 - m1); dn1 += e1; ac1 = fmaf(e1, xv1, ac1);
    }
    if (n < e) {
        float xv = __ldg(x + (size_t)n * H + j);
        float g  = d_gate[n];
        sum += xv; mx = fmaxf(mx, xv);
        if (g > m0) { float sc = __expf(m0 - g); dn0 *= sc; ac0 *= sc; m0 = g; }
        float ev = __expf(g - m0); dn0 += ev; ac0 = fmaf(ev, xv, ac0);
    }

    int cnt = e - s;
    float denom = 0.f, acc = 0.f;
    if (cnt > 0) {
        float M  = fmaxf(m0, m1);
        float s0 = (m0 > -CUDART_INF_F) ? __expf(m0 - M) : 0.f;
        float s1 = (m1 > -CUDART_INF_F) ? __expf(m1 - M) : 0.f;
        denom = dn0 * s0 + dn1 * s1;
        acc   = ac0 * s0 + ac1 * s1;
    }
    float* o = out + (size_t)b * (3 * H);
    o[j]         = sum / fmaxf((float)cnt, 1.f);
    o[H + j]     = mx;
    o[2 * H + j] = (cnt > 0) ? (acc / denom) : 0.f;
}

// ---------------------------------------------------------------------------
extern "C" void kernel_launch(void* const* d_in, const int* in_sizes, int n_in,
                              void* d_out, int out_size) {
    const float* x  = (const float*)d_in[0];
    const float* W1 = (const float*)d_in[1];
    const float* b1 = (const float*)d_in[2];
    const float* W2 = (const float*)d_in[3];
    const int*   bi = (const int*)d_in[5];

    const int N = in_sizes[5];
    const int B = out_size / (3 * H);
    float* out = (float*)d_out;

    static int inited = 0;
    static int sms = 148;
    if (!inited) {
        cudaFuncSetAttribute(gate_mma_kernel,
                             cudaFuncAttributeMaxDynamicSharedMemorySize, SMEM_TOTAL);
        int dev = 0;
        cudaGetDevice(&dev);
        cudaDeviceGetAttribute(&sms, cudaDevAttrMultiProcessorCount, dev);
        inited = 1;
    }

    const int numTiles = (N + TILE_M - 1) / TILE_M;
    const int gateGrid = (2 * sms < numTiles) ? 2 * sms : numTiles;

    init_bounds_kernel<<<(B + 255) / 256, 256>>>(B);
    bounds_kernel<<<(N + 255) / 256, 256>>>(bi, N);
    prep_w1_kernel<<<(H * H + 255) / 256, 256>>>(W1);
    gate_mma_kernel<<<gateGrid, 256, SMEM_TOTAL>>>(x, b1, W2, N);
    reduce_kernel<<<B, H>>>(x, out);
}

// round 16
// speedup vs baseline: 1.2556x; 1.2298x over previous
#include <cuda_runtime.h>
#include <cuda_fp16.h>
#include <math_constants.h>
#include <cstdint>

#define H 128
#define NPAD 1048576
#define SEG_CAP 65536

#define RST32 528                        // fp32 stage row stride bytes (132 floats)
#define RSTB  272                        // fp16 B row stride bytes (136 elems)
#define A32_BUF 33792                    // 64 x 528

// smem layout (bytes), per CTA (x2 CTAs/SM)
#define OFF_B     0                      // 128 x 272 = 34816
#define OFF_A32   34816                  // 2 bufs x 33792 = 67584
#define OFF_SGATE 102400                 // 2 x 64 floats = 512
#define OFF_SB1   102912                 // 512
#define OFF_SW2   103424                 // 512
#define SMEM_TOTAL 103936

__device__ float d_gate[NPAD];
__device__ int   d_seg_start[SEG_CAP];
__device__ int   d_seg_end[SEG_CAP];
__device__ __half d_W1h[H * H];

// ---------------------------------------------------------------------------
__device__ __forceinline__ uint32_t smem_u32(const void* p) {
    uint32_t a;
    asm("{ .reg .u64 t; cvta.to.shared.u64 t, %1; cvt.u32.u64 %0, t; }"
        : "=r"(a) : "l"(p));
    return a;
}
__device__ __forceinline__ void ldsm_x4_t(uint32_t* r, uint32_t addr) {
    asm volatile("ldmatrix.sync.aligned.m8n8.x4.trans.shared.b16 {%0,%1,%2,%3}, [%4];"
                 : "=r"(r[0]), "=r"(r[1]), "=r"(r[2]), "=r"(r[3]) : "r"(addr));
}
__device__ __forceinline__ void mma16816h(float* d, const uint32_t* a,
                                          const uint32_t* b) {
    asm volatile(
        "mma.sync.aligned.m16n8k16.row.col.f32.f16.f16.f32 "
        "{%0,%1,%2,%3}, {%4,%5,%6,%7}, {%8,%9}, {%0,%1,%2,%3};"
        : "+f"(d[0]), "+f"(d[1]), "+f"(d[2]), "+f"(d[3])
        : "r"(a[0]), "r"(a[1]), "r"(a[2]), "r"(a[3]), "r"(b[0]), "r"(b[1]));
}
__device__ __forceinline__ void cp_async16(uint32_t dst, const void* src, int sz) {
    asm volatile("cp.async.cg.shared.global [%0], [%1], 16, %2;"
                 :: "r"(dst), "l"(src), "r"(sz) : "memory");
}
#define CP_COMMIT() asm volatile("cp.async.commit_group;" ::: "memory")
#define CP_WAIT0()  asm volatile("cp.async.wait_group 0;" ::: "memory")
#define CP_WAIT1()  asm volatile("cp.async.wait_group 1;" ::: "memory")

__device__ __forceinline__ float2 lds_f2(uint32_t addr) {
    float2 v;
    asm volatile("ld.shared.v2.f32 {%0,%1}, [%2];"
                 : "=f"(v.x), "=f"(v.y) : "r"(addr));
    return v;
}
__device__ __forceinline__ uint32_t pack_h2(float2 v) {
    __half2 h = __floats2half2_rn(v.x, v.y);
    return *(uint32_t*)&h;
}
__device__ __forceinline__ float tanh_fast(float x) {
    float y;
    asm("tanh.approx.f32 %0, %1;" : "=f"(y) : "f"(x));
    return y;
}
__device__ __forceinline__ float silu_fast(float v) {
    return 0.5f * v * (1.f + tanh_fast(0.5f * v));
}

// ---------------------------------------------------------------------------
// Segment bounds
// ---------------------------------------------------------------------------
__global__ void init_bounds_kernel(int B) {
    int b = blockIdx.x * blockDim.x + threadIdx.x;
    if (b < B) { d_seg_start[b] = -1; d_seg_end[b] = -1; }
}
__global__ void bounds_kernel(const int* __restrict__ bi, int N) {
    int n = blockIdx.x * blockDim.x + threadIdx.x;
    if (n >= N) return;
    int b = bi[n];
    if (n == 0 || bi[n - 1] != b) d_seg_start[b] = n;
    if (n == N - 1 || bi[n + 1] != b) d_seg_end[b] = n + 1;
}

// ---------------------------------------------------------------------------
// W1 -> fp16 (runs once)
// ---------------------------------------------------------------------------
__global__ void prep_w1_kernel(const float* __restrict__ W1) {
    int idx = blockIdx.x * blockDim.x + threadIdx.x;
    if (idx >= H * H) return;
    d_W1h[idx] = __float2half_rn(W1[idx]);
}

__device__ __forceinline__ void issue_cp(const float* __restrict__ x, uint32_t sb,
                                         long t, int buf, int N, int tid) {
    long m0 = t * 64;
    uint32_t dst0 = sb + OFF_A32 + buf * A32_BUF;
#pragma unroll
    for (int c = 0; c < 8; c++) {
        int chunk = c * 256 + tid;           // 2048 chunks of 16B
        int row = chunk >> 5, col16 = chunk & 31;
        long gm = m0 + row;
        const float* src = x + (size_t)(gm < N ? gm : 0) * H + col16 * 4;
        cp_async16(dst0 + row * RST32 + col16 * 16, src, gm < N ? 16 : 0);
    }
    CP_COMMIT();
}

// ---------------------------------------------------------------------------
// Gate kernel: persistent, 2 CTAs/SM. CTA = full 64x128 tile, single fp16
// product (gate = fp16(x) @ fp16(W1)). 256 thr = 8 warps (4M x 2N), warp
// tile 16x64 (acc 32 regs). A floats + B fragments prefetched one k ahead.
// Epilogue uses tanh.approx silu (1 MUFU instead of EX2+RCP).
// ---------------------------------------------------------------------------
__global__ __launch_bounds__(256, 2) void gate_mma_kernel(
    const float* __restrict__ x, const float* __restrict__ b1,
    const float* __restrict__ W2, int N)
{
    extern __shared__ char smem[];
    const uint32_t sb = smem_u32(smem);
    const int tid = threadIdx.x;
    const int wid = tid >> 5, lane = tid & 31;
    const int warp_m = wid & 3;          // rows warp_m*16
    const int warp_n = wid >> 2;         // cols warp_n*64
    const long tile0 = blockIdx.x;
    const long tstride = gridDim.x;

    float* sgate = (float*)(smem + OFF_SGATE);
    float* sb1   = (float*)(smem + OFF_SB1);
    float* sw2   = (float*)(smem + OFF_SW2);
    if (tid < H) { sb1[tid] = b1[tid]; sw2[tid] = W2[tid]; }

    const int numTiles = (N + 63) / 64;

    if (tile0 < numTiles) issue_cp(x, sb, tile0, 0, N, tid);

    // B (W1 fp16) -> smem once: 2048 uint4
#pragma unroll
    for (int c = 0; c < 8; c++) {
        int idx = c * 256 + tid;
        int k = idx >> 4, n8 = (idx & 15) << 3;
        uint32_t off = (uint32_t)k * RSTB + (uint32_t)n8 * 2;
        *(uint4*)(smem + OFF_B + off) = *(const uint4*)(d_W1h + k * H + n8);
    }

    if (tile0 + tstride < numTiles) issue_cp(x, sb, tile0 + tstride, 1, N, tid);

    // per-lane addresses
    const int fr = lane >> 2;            // 0..7
    const int fc = (lane & 3) * 2;       // 0,2,4,6
    const uint32_t a_base = sb + OFF_A32
                          + (uint32_t)(warp_m * 16 + fr) * RST32 + (uint32_t)fc * 4;
    const uint32_t b_base = sb + OFF_B + (uint32_t)(lane & 15) * RSTB
                          + (uint32_t)(warp_n * 64 + (lane >> 4) * 8) * 2;

    int buf = 0;
    for (long t = tile0; t < numTiles; t += tstride, buf ^= 1) {
        const bool hn  = (t + tstride)     < numTiles;
        const bool hnn = (t + 2 * tstride) < numTiles;

        if (hn) { CP_WAIT1(); } else { CP_WAIT0(); }
        __syncthreads();                 // A32[buf] visible; sgate free

        float acc[8][4];
#pragma unroll
        for (int ni = 0; ni < 8; ni++)
#pragma unroll
            for (int r = 0; r < 4; r++) acc[ni][r] = 0.f;

        const uint32_t aK = a_base + (uint32_t)buf * A32_BUF;

        // k=0 A floats + B fragments
        float2 f0 = lds_f2(aK);
        float2 f1 = lds_f2(aK + 8 * RST32);
        float2 f2 = lds_f2(aK + 32);
        float2 f3 = lds_f2(aK + 8 * RST32 + 32);
        uint32_t bfr[2][4][4];           // [pingpong][nb][frag]
#pragma unroll
        for (int nb = 0; nb < 4; nb++)
            ldsm_x4_t(bfr[0][nb], b_base + nb * 32);

#pragma unroll
        for (int k = 0; k < 8; k++) {
            const int cur = k & 1, nxt = cur ^ 1;
            uint32_t ah[4];
            ah[0] = pack_h2(f0);
            ah[1] = pack_h2(f1);
            ah[2] = pack_h2(f2);
            ah[3] = pack_h2(f3);

            if (k < 7) {
                const uint32_t an = aK + (uint32_t)(k + 1) * 64;
                f0 = lds_f2(an);
                f1 = lds_f2(an + 8 * RST32);
                f2 = lds_f2(an + 32);
                f3 = lds_f2(an + 8 * RST32 + 32);
                const uint32_t bn = b_base + (uint32_t)(k + 1) * 16 * RSTB;
#pragma unroll
                for (int nb = 0; nb < 4; nb++)
                    ldsm_x4_t(bfr[nxt][nb], bn + nb * 32);
            }

            // 8 HMMA, each accumulator written once per k-step
#pragma unroll
            for (int nb = 0; nb < 4; nb++) {
                mma16816h(acc[nb * 2],     ah, &bfr[cur][nb][0]);
                mma16816h(acc[nb * 2 + 1], ah, &bfr[cur][nb][2]);
            }
        }

        // ---- epilogue: tanh-silu + dot(W2), warp row-reduce ----
        float part[2] = {0.f, 0.f};
#pragma unroll
        for (int ni = 0; ni < 8; ni++)
#pragma unroll
            for (int r = 0; r < 4; r++) {
                int col = warp_n * 64 + ni * 8 + (lane & 3) * 2 + (r & 1);
                float vv = acc[ni][r] + sb1[col];
                part[r >> 1] = fmaf(silu_fast(vv), sw2[col], part[r >> 1]);
            }
#pragma unroll
        for (int hh = 0; hh < 2; hh++) {
            float p = part[hh];
            p += __shfl_xor_sync(0xFFFFFFFF, p, 1);
            p += __shfl_xor_sync(0xFFFFFFFF, p, 2);
            part[hh] = p;
        }
        if ((lane & 3) == 0) {
#pragma unroll
            for (int hh = 0; hh < 2; hh++) {
                int row = warp_m * 16 + hh * 8 + (lane >> 2);
                sgate[warp_n * 64 + row] = part[hh];
            }
        }
        __syncthreads();                 // A32[buf] reads done; sgate complete

        if (hnn) issue_cp(x, sb, t + 2 * tstride, buf, N, tid);

        if (tid < 64) {
            long gm = t * 64 + tid;
            if (gm < N)
                d_gate[gm] = sgate[tid] + sgate[64 + tid];
        }
    }
}

// ---------------------------------------------------------------------------
// Reduce kernel: per-segment mean/max/attention, 4-way unrolled online
// softmax (4 independent accumulator banks; merged at the end).
// ---------------------------------------------------------------------------
__global__ __launch_bounds__(128) void reduce_kernel(
    const float* __restrict__ x, float* __restrict__ out)
{
    int b = blockIdx.x;
    int j = threadIdx.x;
    int s = d_seg_start[b];
    int e = (s < 0) ? 0 : d_seg_end[b];
    if (s < 0) s = 0;

    float sum = 0.f, mx = -CUDART_INF_F;
    float m[4]  = {-CUDART_INF_F, -CUDART_INF_F, -CUDART_INF_F, -CUDART_INF_F};
    float dn[4] = {0.f, 0.f, 0.f, 0.f};
    float ac[4] = {0.f, 0.f, 0.f, 0.f};

    int n = s;
    for (; n + 4 <= e; n += 4) {
        float xv[4], g[4];
#pragma unroll
        for (int u = 0; u < 4; u++) {
            xv[u] = __ldg(x + (size_t)(n + u) * H + j);
            g[u]  = d_gate[n + u];
        }
#pragma unroll
        for (int u = 0; u < 4; u++) {
            sum += xv[u];
            mx = fmaxf(mx, xv[u]);
            if (g[u] > m[u]) {
                float sc = __expf(m[u] - g[u]);
                dn[u] *= sc; ac[u] *= sc; m[u] = g[u];
            }
            float ev = __expf(g[u] - m[u]);
            dn[u] += ev;
            ac[u] = fmaf(ev, xv[u], ac[u]);
        }
    }
    for (; n < e; ++n) {
        float xv = __ldg(x + (size_t)n * H + j);
        float g  = d_gate[n];
        sum += xv; mx = fmaxf(mx, xv);
        if (g > m[0]) { float sc = __expf(m[0] - g); dn[0] *= sc; ac[0] *= sc; m[0] = g; }
        float ev = __expf(g - m[0]);
        dn[0] += ev; ac[0] = fmaf(ev, xv, ac[0]);
    }

    int cnt = e - s;
    float denom = 0.f, acc = 0.f;
    if (cnt > 0) {
        float M = fmaxf(fmaxf(m[0], m[1]), fmaxf(m[2], m[3]));
#pragma unroll
        for (int u = 0; u < 4; u++) {
            float sc = (m[u] > -CUDART_INF_F) ? __expf(m[u] - M) : 0.f;
            denom = fmaf(dn[u], sc, denom);
            acc   = fmaf(ac[u], sc, acc);
        }
    }
    float* o = out + (size_t)b * (3 * H);
    o[j]         = sum / fmaxf((float)cnt, 1.f);
    o[H + j]     = mx;
    o[2 * H + j] = (cnt > 0) ? (acc / denom) : 0.f;
}

// ---------------------------------------------------------------------------
extern "C" void kernel_launch(void* const* d_in, const int* in_sizes, int n_in,
                              void* d_out, int out_size) {
    const float* x  = (const float*)d_in[0];
    const float* W1 = (const float*)d_in[1];
    const float* b1 = (const float*)d_in[2];
    const float* W2 = (const float*)d_in[3];
    const int*   bi = (const int*)d_in[5];

    const int N = in_sizes[5];
    const int B = out_size / (3 * H);
    float* out = (float*)d_out;

    static int inited = 0;
    static int sms = 148;
    if (!inited) {
        cudaFuncSetAttribute(gate_mma_kernel,
                             cudaFuncAttributeMaxDynamicSharedMemorySize, SMEM_TOTAL);
        int dev = 0;
        cudaGetDevice(&dev);
        cudaDeviceGetAttribute(&sms, cudaDevAttrMultiProcessorCount, dev);
        inited = 1;
    }

    const int numTiles = (N + 63) / 64;
    const int gateGrid = (2 * sms < numTiles) ? 2 * sms : numTiles;

    init_bounds_kernel<<<(B + 255) / 256, 256>>>(B);
    bounds_kernel<<<(N + 255) / 256, 256>>>(bi, N);
    prep_w1_kernel<<<(H * H + 255) / 256, 256>>>(W1);
    gate_mma_kernel<<<gateGrid, 256, SMEM_TOTAL>>>(x, b1, W2, N);
    reduce_kernel<<<B, H>>>(x, out);
}

// round 17
// speedup vs baseline: 1.4047x; 1.1188x over previous
#include <cuda_runtime.h>
#include <cuda_fp16.h>
#include <math_constants.h>
#include <cstdint>

#define H 128
#define NPAD 1048576
#define SEG_CAP 65536

#define RST32 528                        // fp32 stage row stride bytes (132 floats)
#define RSTB  272                        // fp16 B row stride bytes (136 elems)
#define A32_BUF 33792                    // 64 x 528

// smem layout (bytes), per CTA (x2 CTAs/SM)
#define OFF_B     0                      // 128 x 272 = 34816
#define OFF_A32   34816                  // 2 bufs x 33792 = 67584
#define OFF_SGATE 102400                 // 2 x 64 floats = 512
#define OFF_SB1   102912                 // 512
#define OFF_SW2   103424                 // 512
#define SMEM_TOTAL 103936

__device__ float d_gate[NPAD];
__device__ int   d_seg_start[SEG_CAP];
__device__ int   d_seg_end[SEG_CAP];
__device__ float d_seg_gmax[SEG_CAP];
__device__ float d_seg_invdn[SEG_CAP];
__device__ __half d_W1h[H * H];

// ---------------------------------------------------------------------------
__device__ __forceinline__ uint32_t smem_u32(const void* p) {
    uint32_t a;
    asm("{ .reg .u64 t; cvta.to.shared.u64 t, %1; cvt.u32.u64 %0, t; }"
        : "=r"(a) : "l"(p));
    return a;
}
__device__ __forceinline__ void ldsm_x4_t(uint32_t* r, uint32_t addr) {
    asm volatile("ldmatrix.sync.aligned.m8n8.x4.trans.shared.b16 {%0,%1,%2,%3}, [%4];"
                 : "=r"(r[0]), "=r"(r[1]), "=r"(r[2]), "=r"(r[3]) : "r"(addr));
}
__device__ __forceinline__ void mma16816h(float* d, const uint32_t* a,
                                          const uint32_t* b) {
    asm volatile(
        "mma.sync.aligned.m16n8k16.row.col.f32.f16.f16.f32 "
        "{%0,%1,%2,%3}, {%4,%5,%6,%7}, {%8,%9}, {%0,%1,%2,%3};"
        : "+f"(d[0]), "+f"(d[1]), "+f"(d[2]), "+f"(d[3])
        : "r"(a[0]), "r"(a[1]), "r"(a[2]), "r"(a[3]), "r"(b[0]), "r"(b[1]));
}
__device__ __forceinline__ void cp_async16(uint32_t dst, const void* src, int sz) {
    asm volatile("cp.async.cg.shared.global [%0], [%1], 16, %2;"
                 :: "r"(dst), "l"(src), "r"(sz) : "memory");
}
#define CP_COMMIT() asm volatile("cp.async.commit_group;" ::: "memory")
#define CP_WAIT0()  asm volatile("cp.async.wait_group 0;" ::: "memory")
#define CP_WAIT1()  asm volatile("cp.async.wait_group 1;" ::: "memory")

__device__ __forceinline__ float2 lds_f2(uint32_t addr) {
    float2 v;
    asm volatile("ld.shared.v2.f32 {%0,%1}, [%2];"
                 : "=f"(v.x), "=f"(v.y) : "r"(addr));
    return v;
}
__device__ __forceinline__ uint32_t pack_h2(float2 v) {
    __half2 h = __floats2half2_rn(v.x, v.y);
    return *(uint32_t*)&h;
}
__device__ __forceinline__ float tanh_fast(float x) {
    float y;
    asm("tanh.approx.f32 %0, %1;" : "=f"(y) : "f"(x));
    return y;
}
__device__ __forceinline__ float silu_fast(float v) {
    return 0.5f * v * (1.f + tanh_fast(0.5f * v));
}

// ---------------------------------------------------------------------------
// Segment bounds
// ---------------------------------------------------------------------------
__global__ void init_bounds_kernel(int B) {
    int b = blockIdx.x * blockDim.x + threadIdx.x;
    if (b < B) { d_seg_start[b] = -1; d_seg_end[b] = -1; }
}
__global__ void bounds_kernel(const int* __restrict__ bi, int N) {
    int n = blockIdx.x * blockDim.x + threadIdx.x;
    if (n >= N) return;
    int b = bi[n];
    if (n == 0 || bi[n - 1] != b) d_seg_start[b] = n;
    if (n == N - 1 || bi[n + 1] != b) d_seg_end[b] = n + 1;
}

// ---------------------------------------------------------------------------
// W1 -> fp16 (runs once)
// ---------------------------------------------------------------------------
__global__ void prep_w1_kernel(const float* __restrict__ W1) {
    int idx = blockIdx.x * blockDim.x + threadIdx.x;
    if (idx >= H * H) return;
    d_W1h[idx] = __float2half_rn(W1[idx]);
}

__device__ __forceinline__ void issue_cp(const float* __restrict__ x, uint32_t sb,
                                         long t, int buf, int N, int tid) {
    long m0 = t * 64;
    uint32_t dst0 = sb + OFF_A32 + buf * A32_BUF;
#pragma unroll
    for (int c = 0; c < 8; c++) {
        int chunk = c * 256 + tid;           // 2048 chunks of 16B
        int row = chunk >> 5, col16 = chunk & 31;
        long gm = m0 + row;
        const float* src = x + (size_t)(gm < N ? gm : 0) * H + col16 * 4;
        cp_async16(dst0 + row * RST32 + col16 * 16, src, gm < N ? 16 : 0);
    }
    CP_COMMIT();
}

// ---------------------------------------------------------------------------
// Gate kernel: persistent, 2 CTAs/SM. CTA = full 64x128 tile, single fp16
// product (gate = fp16(x) @ fp16(W1)). 256 thr = 8 warps (4M x 2N), warp
// tile 16x64. A floats + B fragments prefetched one k ahead; tanh silu.
// ---------------------------------------------------------------------------
__global__ __launch_bounds__(256, 2) void gate_mma_kernel(
    const float* __restrict__ x, const float* __restrict__ b1,
    const float* __restrict__ W2, int N)
{
    extern __shared__ char smem[];
    const uint32_t sb = smem_u32(smem);
    const int tid = threadIdx.x;
    const int wid = tid >> 5, lane = tid & 31;
    const int warp_m = wid & 3;          // rows warp_m*16
    const int warp_n = wid >> 2;         // cols warp_n*64
    const long tile0 = blockIdx.x;
    const long tstride = gridDim.x;

    float* sgate = (float*)(smem + OFF_SGATE);
    float* sb1   = (float*)(smem + OFF_SB1);
    float* sw2   = (float*)(smem + OFF_SW2);
    if (tid < H) { sb1[tid] = b1[tid]; sw2[tid] = W2[tid]; }

    const int numTiles = (N + 63) / 64;

    if (tile0 < numTiles) issue_cp(x, sb, tile0, 0, N, tid);

    // B (W1 fp16) -> smem once: 2048 uint4
#pragma unroll
    for (int c = 0; c < 8; c++) {
        int idx = c * 256 + tid;
        int k = idx >> 4, n8 = (idx & 15) << 3;
        uint32_t off = (uint32_t)k * RSTB + (uint32_t)n8 * 2;
        *(uint4*)(smem + OFF_B + off) = *(const uint4*)(d_W1h + k * H + n8);
    }

    if (tile0 + tstride < numTiles) issue_cp(x, sb, tile0 + tstride, 1, N, tid);

    // per-lane addresses
    const int fr = lane >> 2;            // 0..7
    const int fc = (lane & 3) * 2;       // 0,2,4,6
    const uint32_t a_base = sb + OFF_A32
                          + (uint32_t)(warp_m * 16 + fr) * RST32 + (uint32_t)fc * 4;
    const uint32_t b_base = sb + OFF_B + (uint32_t)(lane & 15) * RSTB
                          + (uint32_t)(warp_n * 64 + (lane >> 4) * 8) * 2;

    int buf = 0;
    for (long t = tile0; t < numTiles; t += tstride, buf ^= 1) {
        const bool hn  = (t + tstride)     < numTiles;
        const bool hnn = (t + 2 * tstride) < numTiles;

        if (hn) { CP_WAIT1(); } else { CP_WAIT0(); }
        __syncthreads();                 // A32[buf] visible; sgate free

        float acc[8][4];
#pragma unroll
        for (int ni = 0; ni < 8; ni++)
#pragma unroll
            for (int r = 0; r < 4; r++) acc[ni][r] = 0.f;

        const uint32_t aK = a_base + (uint32_t)buf * A32_BUF;

        // k=0 A floats + B fragments
        float2 f0 = lds_f2(aK);
        float2 f1 = lds_f2(aK + 8 * RST32);
        float2 f2 = lds_f2(aK + 32);
        float2 f3 = lds_f2(aK + 8 * RST32 + 32);
        uint32_t bfr[2][4][4];           // [pingpong][nb][frag]
#pragma unroll
        for (int nb = 0; nb < 4; nb++)
            ldsm_x4_t(bfr[0][nb], b_base + nb * 32);

#pragma unroll
        for (int k = 0; k < 8; k++) {
            const int cur = k & 1, nxt = cur ^ 1;
            uint32_t ah[4];
            ah[0] = pack_h2(f0);
            ah[1] = pack_h2(f1);
            ah[2] = pack_h2(f2);
            ah[3] = pack_h2(f3);

            if (k < 7) {
                const uint32_t an = aK + (uint32_t)(k + 1) * 64;
                f0 = lds_f2(an);
                f1 = lds_f2(an + 8 * RST32);
                f2 = lds_f2(an + 32);
                f3 = lds_f2(an + 8 * RST32 + 32);
                const uint32_t bn = b_base + (uint32_t)(k + 1) * 16 * RSTB;
#pragma unroll
                for (int nb = 0; nb < 4; nb++)
                    ldsm_x4_t(bfr[nxt][nb], bn + nb * 32);
            }

#pragma unroll
            for (int nb = 0; nb < 4; nb++) {
                mma16816h(acc[nb * 2],     ah, &bfr[cur][nb][0]);
                mma16816h(acc[nb * 2 + 1], ah, &bfr[cur][nb][2]);
            }
        }

        // ---- epilogue: tanh-silu + dot(W2), warp row-reduce ----
        float part[2] = {0.f, 0.f};
#pragma unroll
        for (int ni = 0; ni < 8; ni++)
#pragma unroll
            for (int r = 0; r < 4; r++) {
                int col = warp_n * 64 + ni * 8 + (lane & 3) * 2 + (r & 1);
                float vv = acc[ni][r] + sb1[col];
                part[r >> 1] = fmaf(silu_fast(vv), sw2[col], part[r >> 1]);
            }
#pragma unroll
        for (int hh = 0; hh < 2; hh++) {
            float p = part[hh];
            p += __shfl_xor_sync(0xFFFFFFFF, p, 1);
            p += __shfl_xor_sync(0xFFFFFFFF, p, 2);
            part[hh] = p;
        }
        if ((lane & 3) == 0) {
#pragma unroll
            for (int hh = 0; hh < 2; hh++) {
                int row = warp_m * 16 + hh * 8 + (lane >> 2);
                sgate[warp_n * 64 + row] = part[hh];
            }
        }
        __syncthreads();                 // A32[buf] reads done; sgate complete

        if (hnn) issue_cp(x, sb, t + 2 * tstride, buf, N, tid);

        if (tid < 64) {
            long gm = t * 64 + tid;
            if (gm < N)
                d_gate[gm] = sgate[tid] + sgate[64 + tid];
        }
    }
}

// ---------------------------------------------------------------------------
// Softmax stats: one warp per segment -> gmax, 1/denom (exact ref math)
// ---------------------------------------------------------------------------
__global__ __launch_bounds__(256) void gate_stats_kernel(int B) {
    int w = (blockIdx.x * blockDim.x + threadIdx.x) >> 5;
    int lane = threadIdx.x & 31;
    if (w >= B) return;
    int s = d_seg_start[w];
    int e = (s < 0) ? 0 : d_seg_end[w];
    if (s < 0) s = 0;

    float m = -CUDART_INF_F;
    for (int n = s + lane; n < e; n += 32) m = fmaxf(m, d_gate[n]);
#pragma unroll
    for (int o = 16; o; o >>= 1) m = fmaxf(m, __shfl_xor_sync(0xFFFFFFFF, m, o));

    float dn = 0.f;
    for (int n = s + lane; n < e; n += 32) dn += __expf(d_gate[n] - m);
#pragma unroll
    for (int o = 16; o; o >>= 1) dn += __shfl_xor_sync(0xFFFFFFFF, dn, o);

    if (lane == 0) {
        d_seg_gmax[w]  = m;
        d_seg_invdn[w] = (e > s) ? (1.f / dn) : 0.f;
    }
}

// ---------------------------------------------------------------------------
// Reduce kernel: streaming mean/max/attn with precomputed softmax stats.
// Per 32-row chunk, lanes 0-31 stage the weights in smem (double-buffered,
// one barrier per chunk); all 128 threads then run a branch-free fma loop.
// ---------------------------------------------------------------------------
__global__ __launch_bounds__(128) void reduce_kernel(
    const float* __restrict__ x, float* __restrict__ out)
{
    __shared__ float w[2][32];
    int b = blockIdx.x;
    int j = threadIdx.x;
    int s = d_seg_start[b];
    int e = (s < 0) ? 0 : d_seg_end[b];
    if (s < 0) s = 0;

    const float gmax  = d_seg_gmax[b];
    const float invdn = d_seg_invdn[b];

    float sum = 0.f, mx = -CUDART_INF_F, acc = 0.f;

    int par = 0;
    for (int n0 = s; n0 < e; n0 += 32, par ^= 1) {
        if (j < 32) {
            int n = n0 + j;
            w[par][j] = (n < e) ? __expf(d_gate[n] - gmax) : 0.f;
        }
        __syncthreads();
        const int lim = (e - n0 < 32) ? (e - n0) : 32;
        const float* xp = x + (size_t)n0 * H + j;
        for (int i = 0; i < lim; i++) {
            float xv = __ldg(xp + (size_t)i * H);
            sum += xv;
            mx = fmaxf(mx, xv);
            acc = fmaf(w[par][i], xv, acc);
        }
    }

    int cnt = e - s;
    float* o = out + (size_t)b * (3 * H);
    o[j]         = sum / fmaxf((float)cnt, 1.f);
    o[H + j]     = mx;
    o[2 * H + j] = acc * invdn;
}

// ---------------------------------------------------------------------------
extern "C" void kernel_launch(void* const* d_in, const int* in_sizes, int n_in,
                              void* d_out, int out_size) {
    const float* x  = (const float*)d_in[0];
    const float* W1 = (const float*)d_in[1];
    const float* b1 = (const float*)d_in[2];
    const float* W2 = (const float*)d_in[3];
    const int*   bi = (const int*)d_in[5];

    const int N = in_sizes[5];
    const int B = out_size / (3 * H);
    float* out = (float*)d_out;

    static int inited = 0;
    static int sms = 148;
    if (!inited) {
        cudaFuncSetAttribute(gate_mma_kernel,
                             cudaFuncAttributeMaxDynamicSharedMemorySize, SMEM_TOTAL);
        int dev = 0;
        cudaGetDevice(&dev);
        cudaDeviceGetAttribute(&sms, cudaDevAttrMultiProcessorCount, dev);
        inited = 1;
    }

    const int numTiles = (N + 63) / 64;
    const int gateGrid = (2 * sms < numTiles) ? 2 * sms : numTiles;

    init_bounds_kernel<<<(B + 255) / 256, 256>>>(B);
    bounds_kernel<<<(N + 255) / 256, 256>>>(bi, N);
    prep_w1_kernel<<<(H * H + 255) / 256, 256>>>(W1);
    gate_mma_kernel<<<gateGrid, 256, SMEM_TOTAL>>>(x, b1, W2, N);
    gate_stats_kernel<<<(B * 32 + 255) / 256, 256>>>(B);
    reduce_kernel<<<B, H>>>(x, out);
}